// round 1
// baseline (speedup 1.0000x reference)
#include <cuda_runtime.h>
#include <cuda_bf16.h>
#include <math.h>

// ---------------------------------------------------------------------------
// Problem constants
// ---------------------------------------------------------------------------
#define B_    256
#define K_    4
#define CIN_  256
#define CV_   128
#define COUT_ 256
#define HW_   256      // 16*16
#define LOG2PI 1.8378770664093453f

// Output layout (concatenated flat float32):
// out(16777216), z(8388608), logprob_p(33554432), logprob_q(8388608),
// kl_total(1), q_mu(8388608), q_lv(8388608), y(1024), cross_entropy(1)
#define OFF_OUT 0
#define OFF_Z   16777216
#define OFF_LPP 25165824
#define OFF_LPQ 58720256
#define OFF_KLT 67108864
#define OFF_QMU 67108865
#define OFF_QLV 75497473
#define OFF_Y   83886081
#define OFF_CE  83887105

// ---------------------------------------------------------------------------
// Scratch (device-global; no runtime allocation)
// ---------------------------------------------------------------------------
__device__ float  g_h[B_ * CV_ * HW_];        // qy conv output (relu)     33.5MB
__device__ float  g_qmod[B_ * CIN_ * HW_];    // gamma*q+beta              67MB
__device__ float  g_t1[B_ * 2 * CV_ * HW_];   // relu(conv(qmod,qz1))      67MB
__device__ float  g_qz[B_ * 2 * CV_ * HW_];   // conv(t1,qz2)              67MB
__device__ float  g_logits[B_ * K_];
__device__ float  g_gamma[B_ * CIN_];
__device__ float  g_beta[B_ * CIN_];
__device__ double g_kl_sum;
__device__ double g_js_mean;

// ---------------------------------------------------------------------------
// Helpers
// ---------------------------------------------------------------------------
__device__ __forceinline__ float clamp10(float v) {
    return fminf(fmaxf(v, -10.0f), 10.0f);
}
__device__ __forceinline__ float std_from_lv(float lv) {
    return (lv < 0.0f) ? expf(0.5f * lv) : (1.0f + lv);
}
__device__ __forceinline__ float logstd_from_lv(float lv) {
    return (lv < 0.0f) ? 0.5f * lv : log1pf(lv);
}

// ---------------------------------------------------------------------------
// 3x3 same conv, NCHW, 16x16 spatial.
// Block: 256 threads = 16x16 pixels. Each block: 2 images x 16 out channels.
// grid.x = COUT/16, grid.y = B/2
// ---------------------------------------------------------------------------
template <int CIN, int COUT, bool RELU>
__global__ __launch_bounds__(256)
void conv3x3_kernel(const float* __restrict__ in, const float* __restrict__ w,
                    const float* __restrict__ bias, float* __restrict__ out) {
    constexpr int CT = 8;   // cin tile
    constexpr int OT = 16;  // cout tile
    __shared__ float s_in[2 * CT * 324];  // 2 imgs * 8 ch * 18*18
    __shared__ float s_w[OT * CT * 9];    // [co][ci][t]

    const int tid = threadIdx.x;
    const int ty = tid >> 4;
    const int tx = tid & 15;
    const int cout0 = blockIdx.x * OT;
    const int b0 = blockIdx.y * 2;

    float acc0[OT], acc1[OT];
#pragma unroll
    for (int i = 0; i < OT; i++) { acc0[i] = 0.0f; acc1[i] = 0.0f; }

    for (int cb = 0; cb < CIN; cb += CT) {
        __syncthreads();
        // load input halo tiles: 2*8*324 = 5184 floats
        for (int i = tid; i < 2 * CT * 324; i += 256) {
            int img = i / (CT * 324);
            int rem = i - img * (CT * 324);
            int ci = rem / 324;
            int p = rem - ci * 324;
            int yy = p / 18;
            int xx = p - yy * 18;
            int gy = yy - 1, gx = xx - 1;
            float v = 0.0f;
            if (gy >= 0 && gy < 16 && gx >= 0 && gx < 16)
                v = in[(((b0 + img) * CIN + cb + ci) * 16 + gy) * 16 + gx];
            s_in[i] = v;
        }
        // load weights: 16*8*9 = 1152 floats
        for (int i = tid; i < OT * CT * 9; i += 256) {
            int co = i / (CT * 9);
            int rem = i - co * (CT * 9);
            s_w[i] = w[(cout0 + co) * CIN * 9 + cb * 9 + rem];
        }
        __syncthreads();

        for (int ci = 0; ci < CT; ci++) {
            float a0[9], a1[9];
            const float* p0 = &s_in[ci * 324 + ty * 18 + tx];
            const float* p1 = &s_in[(CT + ci) * 324 + ty * 18 + tx];
#pragma unroll
            for (int dy = 0; dy < 3; dy++)
#pragma unroll
                for (int dx = 0; dx < 3; dx++) {
                    a0[dy * 3 + dx] = p0[dy * 18 + dx];
                    a1[dy * 3 + dx] = p1[dy * 18 + dx];
                }
            const float* wp = &s_w[ci * 9];
#pragma unroll
            for (int co = 0; co < OT; co++) {
#pragma unroll
                for (int t = 0; t < 9; t++) {
                    float wv = wp[co * CT * 9 + t];
                    acc0[co] += wv * a0[t];
                    acc1[co] += wv * a1[t];
                }
            }
        }
    }

#pragma unroll
    for (int co = 0; co < OT; co++) {
        float bz = bias[cout0 + co];
        float v0 = acc0[co] + bz;
        float v1 = acc1[co] + bz;
        if (RELU) { v0 = fmaxf(v0, 0.0f); v1 = fmaxf(v1, 0.0f); }
        out[((b0 + 0) * COUT + cout0 + co) * HW_ + tid] = v0;
        out[((b0 + 1) * COUT + cout0 + co) * HW_ + tid] = v1;
    }
}

// ---------------------------------------------------------------------------
// qy_lin: logits[b,k] = sum_i h[b,i]*w[k,i] + bias[k]. One block per b.
// ---------------------------------------------------------------------------
__global__ __launch_bounds__(256)
void qy_lin_kernel(const float* __restrict__ h, const float* __restrict__ w,
                   const float* __restrict__ bias, float* __restrict__ logits) {
    const int b = blockIdx.x;
    const int tid = threadIdx.x;
    const int N = CV_ * HW_;  // 32768
    float acc[K_] = {0, 0, 0, 0};
    const float* hb = h + b * N;
    for (int i = tid; i < N; i += 256) {
        float hv = hb[i];
#pragma unroll
        for (int k = 0; k < K_; k++) acc[k] += hv * w[k * N + i];
    }
    __shared__ float red[256];
#pragma unroll
    for (int k = 0; k < K_; k++) {
        red[tid] = acc[k];
        __syncthreads();
        for (int s = 128; s > 0; s >>= 1) {
            if (tid < s) red[tid] += red[tid + s];
            __syncthreads();
        }
        if (tid == 0) logits[b * K_ + k] = red[0] + bias[k];
        __syncthreads();
    }
}

// ---------------------------------------------------------------------------
// Per-batch small work: gumbel softmax y, cross_entropy, js, gamma/beta.
// Single block of 256 threads (one thread per batch element).
// ---------------------------------------------------------------------------
__global__ __launch_bounds__(256)
void small_kernel(const float* __restrict__ logits, const float* __restrict__ u,
                  const int* __restrict__ label,
                  const float* __restrict__ gamma_w, const float* __restrict__ gamma_b,
                  const float* __restrict__ beta_w, const float* __restrict__ beta_b,
                  float* __restrict__ gamma, float* __restrict__ beta,
                  float* __restrict__ out) {
    const int b = threadIdx.x;
    float l[K_], y[K_];
#pragma unroll
    for (int k = 0; k < K_; k++) l[k] = logits[b * K_ + k];

    // gumbel softmax (TAU=1)
    float s[K_];
    float mx = -1e30f;
#pragma unroll
    for (int k = 0; k < K_; k++) {
        float uu = u[b * K_ + k];
        float g = -logf(-logf(uu));
        s[k] = l[k] + g;
        mx = fmaxf(mx, s[k]);
    }
    float sum = 0.0f;
#pragma unroll
    for (int k = 0; k < K_; k++) { y[k] = expf(s[k] - mx); sum += y[k]; }
    float inv = 1.0f / sum;
#pragma unroll
    for (int k = 0; k < K_; k++) {
        y[k] *= inv;
        out[OFF_Y + b * K_ + k] = y[k];
    }

    // cross entropy: lse(l) - l[label]
    float mx2 = fmaxf(fmaxf(l[0], l[1]), fmaxf(l[2], l[3]));
    float se = 0.0f;
#pragma unroll
    for (int k = 0; k < K_; k++) se += expf(l[k] - mx2);
    float lse = logf(se) + mx2;
    int lbl = label[b];
    float ce_b = lse - l[lbl];

    // JS to uniform prior 1/K
    const float prior = 1.0f / K_;
    float t1 = 0.0f, t2 = 0.0f;
#pragma unroll
    for (int k = 0; k < K_; k++) {
        float m = 0.5f * (y[k] + prior);
        t1 += y[k] * logf(y[k] / (m + 1e-10f));
        t2 += prior * logf(prior / (m + 1e-10f));
    }
    float js_b = 0.5f * t1 + 0.5f * t2;

    // gamma / beta (B x 256)
    for (int c = 0; c < CIN_; c++) {
        float gw = gamma_w[c * K_ + 0] * l[0] + gamma_w[c * K_ + 1] * l[1] +
                   gamma_w[c * K_ + 2] * l[2] + gamma_w[c * K_ + 3] * l[3];
        float bw = beta_w[c * K_ + 0] * l[0] + beta_w[c * K_ + 1] * l[1] +
                   beta_w[c * K_ + 2] * l[2] + beta_w[c * K_ + 3] * l[3];
        gamma[b * CIN_ + c] = gw + gamma_b[c];
        beta[b * CIN_ + c] = bw + beta_b[c];
    }

    // reduce ce and js over 256 threads
    __shared__ double r1[256], r2[256];
    r1[b] = (double)ce_b;
    r2[b] = (double)js_b;
    __syncthreads();
    for (int st = 128; st > 0; st >>= 1) {
        if (b < st) { r1[b] += r1[b + st]; r2[b] += r2[b + st]; }
        __syncthreads();
    }
    if (b == 0) {
        out[OFF_CE] = (float)(r1[0] / (double)B_);
        g_js_mean = r2[0] / (double)B_;
        g_kl_sum = 0.0;
    }
}

// ---------------------------------------------------------------------------
// q_mod = gamma[b,c]*q + beta[b,c]
// ---------------------------------------------------------------------------
__global__ __launch_bounds__(256)
void qmod_kernel(const float* __restrict__ q, const float* __restrict__ gamma,
                 const float* __restrict__ beta, float* __restrict__ qmod) {
    int idx = blockIdx.x * 256 + threadIdx.x;  // B*CIN*HW threads
    int bc = idx >> 8;  // b*CIN + c
    qmod[idx] = gamma[bc] * q[idx] + beta[bc];
}

// ---------------------------------------------------------------------------
// z / q_mu / q_lv / logprob_q. (z - q_mu)/q_std == eps exactly.
// ---------------------------------------------------------------------------
__global__ __launch_bounds__(256)
void z_kernel(const float* __restrict__ qz, const float* __restrict__ eps,
              float* __restrict__ out) {
    int idx = blockIdx.x * 256 + threadIdx.x;  // B*CV*HW
    int b = idx >> 15;            // / 32768
    int r = idx & 32767;
    int c = r >> 8;
    int pix = r & 255;
    float mu = clamp10(qz[((b * (2 * CV_) + c) << 8) + pix]);
    float lv = clamp10(qz[((b * (2 * CV_) + CV_ + c) << 8) + pix]);
    float sd = std_from_lv(lv);
    float lsd = logstd_from_lv(lv);
    float e = eps[idx];
    float z = mu + sd * e;
    out[OFF_Z + idx] = z;
    out[OFF_QMU + idx] = mu;
    out[OFF_QLV + idx] = lv;
    out[OFF_LPQ + idx] = -0.5f * e * e - lsd - 0.5f * LOG2PI;
}

// ---------------------------------------------------------------------------
// logprob_p (all K, transposed layout [b,c,pix,k]) + fused KL(label) reduce
// ---------------------------------------------------------------------------
__global__ __launch_bounds__(256)
void pk_kernel(const float* __restrict__ p, const int* __restrict__ label,
               float* __restrict__ out) {
    int idx = blockIdx.x * 256 + threadIdx.x;  // B*CV*HW threads
    int b = idx >> 15;
    int r = idx & 32767;
    int c = r >> 8;
    int pix = r & 255;
    int lbl = label[b];

    float z = out[OFF_Z + idx];
    float qm = out[OFF_QMU + idx];
    float qlv = out[OFF_QLV + idx];
    float qs = std_from_lv(qlv);
    float lqs = logstd_from_lv(qlv);

    float4 lp;
    float klv = 0.0f;
#pragma unroll
    for (int k = 0; k < K_; k++) {
        int base = ((b * (2 * K_ * CV_) + k * CV_ + c) << 8) + pix;
        float pm = clamp10(p[base]);
        float plv = clamp10(p[base + (K_ * CV_ << 8)]);  // +512 channels
        float ps = std_from_lv(plv);
        float lps = logstd_from_lv(plv);
        float inv_ps = 1.0f / ps;
        float d = (z - pm) * inv_ps;
        float v = -0.5f * d * d - lps - 0.5f * LOG2PI;
        if (k == 0) lp.x = v;
        else if (k == 1) lp.y = v;
        else if (k == 2) lp.z = v;
        else lp.w = v;
        if (k == lbl) {
            float dd = qm - pm;
            klv = lps - lqs + (qs * qs + dd * dd) * (0.5f * inv_ps * inv_ps) - 0.5f;
        }
    }
    reinterpret_cast<float4*>(out + OFF_LPP)[idx] = lp;

    __shared__ float red[256];
    red[threadIdx.x] = klv;
    __syncthreads();
    for (int s = 128; s > 0; s >>= 1) {
        if (threadIdx.x < s) red[threadIdx.x] += red[threadIdx.x + s];
        __syncthreads();
    }
    if (threadIdx.x == 0) atomicAdd(&g_kl_sum, (double)red[0]);
}

__global__ void finalize_kernel(float* __restrict__ out) {
    out[OFF_KLT] = (float)(g_kl_sum / (double)(B_ * CV_ * HW_) + g_js_mean);
}

// ---------------------------------------------------------------------------
// Launch
// ---------------------------------------------------------------------------
extern "C" void kernel_launch(void* const* d_in, const int* in_sizes, int n_in,
                              void* d_out, int out_size) {
    const float* p_params = (const float*)d_in[0];
    const float* q_params = (const float*)d_in[1];
    const int*   label    = (const int*)d_in[2];
    const float* eps      = (const float*)d_in[3];
    const float* u_gumbel = (const float*)d_in[4];
    const float* qy_conv_w = (const float*)d_in[5];
    const float* qy_conv_b = (const float*)d_in[6];
    const float* qy_lin_w  = (const float*)d_in[7];
    const float* qy_lin_b  = (const float*)d_in[8];
    const float* gamma_w   = (const float*)d_in[9];
    const float* gamma_b   = (const float*)d_in[10];
    const float* beta_w    = (const float*)d_in[11];
    const float* beta_b    = (const float*)d_in[12];
    const float* qz1_w     = (const float*)d_in[13];
    const float* qz1_b     = (const float*)d_in[14];
    const float* qz2_w     = (const float*)d_in[15];
    const float* qz2_b     = (const float*)d_in[16];
    const float* out_w     = (const float*)d_in[17];
    const float* out_b     = (const float*)d_in[18];
    float* out = (float*)d_out;

    float *h, *qmod, *t1, *qz, *logits, *gamma, *beta;
    cudaGetSymbolAddress((void**)&h, g_h);
    cudaGetSymbolAddress((void**)&qmod, g_qmod);
    cudaGetSymbolAddress((void**)&t1, g_t1);
    cudaGetSymbolAddress((void**)&qz, g_qz);
    cudaGetSymbolAddress((void**)&logits, g_logits);
    cudaGetSymbolAddress((void**)&gamma, g_gamma);
    cudaGetSymbolAddress((void**)&beta, g_beta);

    // 1) h = relu(conv(q_params, qy_conv))
    conv3x3_kernel<CIN_, CV_, true><<<dim3(CV_ / 16, B_ / 2), 256>>>(
        q_params, qy_conv_w, qy_conv_b, h);
    // 2) qy_logits
    qy_lin_kernel<<<B_, 256>>>(h, qy_lin_w, qy_lin_b, logits);
    // 3) y / ce / js / gamma / beta
    small_kernel<<<1, 256>>>(logits, u_gumbel, label, gamma_w, gamma_b,
                             beta_w, beta_b, gamma, beta, out);
    // 4) q_mod
    qmod_kernel<<<(B_ * CIN_ * HW_) / 256, 256>>>(q_params, gamma, beta, qmod);
    // 5) t1 = relu(conv(q_mod, qz1))
    conv3x3_kernel<CIN_, 2 * CV_, true><<<dim3((2 * CV_) / 16, B_ / 2), 256>>>(
        qmod, qz1_w, qz1_b, t1);
    // 6) qz_params = conv(t1, qz2)
    conv3x3_kernel<2 * CV_, 2 * CV_, false><<<dim3((2 * CV_) / 16, B_ / 2), 256>>>(
        t1, qz2_w, qz2_b, qz);
    // 7) z / q_mu / q_lv / logprob_q
    z_kernel<<<(B_ * CV_ * HW_) / 256, 256>>>(qz, eps, out);
    // 8) out = conv(z, out_w)
    conv3x3_kernel<CV_, COUT_, false><<<dim3(COUT_ / 16, B_ / 2), 256>>>(
        out + OFF_Z, out_w, out_b, out + OFF_OUT);
    // 9) logprob_p + kl
    pk_kernel<<<(B_ * CV_ * HW_) / 256, 256>>>(p_params, label, out);
    // 10) kl_total
    finalize_kernel<<<1, 1>>>(out);
}